// round 13
// baseline (speedup 1.0000x reference)
#include <cuda_runtime.h>
#include <cuda_fp16.h>
#include <cstdint>

// ---------------------------------------------------------------------------
// MultiLevelFeatureSampler on GB300 (sm_103a via base-target sm_103 SASS)
//
// Per point: D[128x256] = P[128x83] @ W^T (+ bias); P = gather of 83 taps.
// Two-product fp16 scheme: A -> fp16, B -> fp16 split (bh, bl);
// D = ah*bh + ah*bl  (rel_err ~2e-4, measured R11).
//
// R13: R11 structure (warps 4x4, warp tile 32x32, hh halves) with:
//  - A fragments hoisted across the two N-halves (ks-outer loop): A ldsm
//    traffic halves; all operand register arrays stay independent (the R12
//    regression was WAR serialization from b-register reuse).
//  - half2-packed convert: one 4B STS per 2 taps (-48% STS).
// Persistent CTAs (grid=148, 512 thr); gather of p+1 = fire-and-forget
// cp.async into raw fp32 smem during MMA of p; resident B; st.global.cs.
// ---------------------------------------------------------------------------

#define NSM   148
#define NPTS_TOTAL 2048
#define CCH   128
#define DTOT  83
#define GTOT  (CCH * DTOT)     // 10624 gather elements per point
#define STRD  104              // row stride in fp16 (208 B, ldmatrix conflict-free)
#define NOUT  256
#define NTHR  512

#define H0 93
#define W0 305
#define H1 47
#define W1 153
#define H2 24
#define W2 77

// ---- smem layout (bytes) ----
#define OFF_TAPP    0                              // 83 * 8B tap base pointers
#define OFF_TAPS    672                            // 83 * 4B channel strides
#define OFF_BIAS    1008                           // 256 * 4B -> ends 2032
#define OFF_A       2048                           // 128 x 208B = 26624 (fp16)
#define OFF_RAW     (OFF_A + CCH * STRD * 2)       // 28672, 10624 fp32 = 42496
#define OFF_BH      (OFF_RAW + GTOT * 4)           // 71168 (256 x 208B fp16)
#define OFF_BL      (OFF_BH + NOUT * STRD * 2)     // 124416
#define SMEM_TOTAL  (OFF_BL + NOUT * STRD * 2)     // 177664 (~173.5 KB)

// W split-fp16 scratch, [0]=hi, [1]=lo, row-major 256 x STRD (pads zeroed)
__device__ __align__(16) __half g_B[2][NOUT * STRD];

// ---------------------------------------------------------------------------
__device__ __forceinline__ uint32_t smem_u32(const void* p) {
    uint32_t a;
    asm("{ .reg .u64 t; cvta.to.shared.u64 t, %1; cvt.u32.u64 %0, t; }"
        : "=r"(a) : "l"(p));
    return a;
}

__device__ __forceinline__ void cp16(uint32_t dst, const void* src) {
    asm volatile("cp.async.cg.shared.global [%0], [%1], 16;"
                 :: "r"(dst), "l"(src) : "memory");
}

__device__ __forceinline__ void cp4(uint32_t dst, const void* src) {
    asm volatile("cp.async.ca.shared.global [%0], [%1], 4;"
                 :: "r"(dst), "l"(src) : "memory");
}

__device__ __forceinline__ void ldsm4(uint32_t* r, uint32_t addr) {
    asm volatile("ldmatrix.sync.aligned.m8n8.x4.shared.b16 {%0,%1,%2,%3}, [%4];"
                 : "=r"(r[0]), "=r"(r[1]), "=r"(r[2]), "=r"(r[3]) : "r"(addr));
}

__device__ __forceinline__ void hmma(float* c, const uint32_t* a, const uint32_t* b) {
    asm volatile(
        "mma.sync.aligned.m16n8k16.row.col.f32.f16.f16.f32 "
        "{%0,%1,%2,%3}, {%4,%5,%6,%7}, {%8,%9}, {%0,%1,%2,%3};"
        : "+f"(c[0]), "+f"(c[1]), "+f"(c[2]), "+f"(c[3])
        : "r"(a[0]), "r"(a[1]), "r"(a[2]), "r"(a[3]), "r"(b[0]), "r"(b[1]));
}

__device__ __forceinline__ void stcs2(float* p, float x, float y) {
    asm volatile("st.global.cs.v2.f32 [%0], {%1, %2};"
                 :: "l"(p), "f"(x), "f"(y) : "memory");
}

// Per-tap gather metadata for point pn (called with d < 83)
__device__ __forceinline__ void compute_taps(char* smem, int d, int pn,
                                             const float* __restrict__ points,
                                             const float* __restrict__ feat0,
                                             const float* __restrict__ feat1,
                                             const float* __restrict__ feat2) {
    const float* f; int H, Wd, ks, dd;
    if (d < 49)      { f = feat0; H = H0; Wd = W0; ks = 7; dd = d; }
    else if (d < 74) { f = feat1; H = H1; Wd = W1; ks = 5; dd = d - 49; }
    else             { f = feat2; H = H2; Wd = W2; ks = 3; dd = d - 74; }
    int half = ks >> 1;
    int jj = dd / ks - half;
    int kk = dd % ks - half;
    int bi = pn >> 9;
    float px = points[pn * 2 + 0];
    float py = points[pn * 2 + 1];
    float x = fminf(fmaxf(px * (float)(Wd - 1), 0.f), (float)(Wd - 1));
    float y = fminf(fmaxf(py * (float)(H  - 1), 0.f), (float)(H  - 1));
    int ox = (int)floorf(fminf(fmaxf(x + (float)kk, 0.f), (float)(Wd - 1)));
    int oy = (int)floorf(fminf(fmaxf(y + (float)jj, 0.f), (float)(H  - 1)));
    *(int*)(smem + OFF_TAPS + d * 4) = H * Wd;
    *(const float**)(smem + OFF_TAPP + d * 8) =
        f + (size_t)bi * CCH * H * Wd + (oy * Wd + ox);
}

// Issue all gather cp.asyncs for one point into the raw buffer (no waiting).
// 512 threads: e = tid + 512*i;  512 = 6*83 + 14.
__device__ __forceinline__ void issue_gather(char* smem, uint32_t raw, int tid) {
    int c = tid / DTOT;
    int d = tid - c * DTOT;
    #pragma unroll 7
    for (int i = 0; i < 21; ++i) {
        int e = tid + NTHR * i;
        if (e < GTOT) {
            const float* bp = *(const float* const*)(smem + OFF_TAPP + d * 8);
            int st = *(const int*)(smem + OFF_TAPS + d * 4);
            cp4(raw + e * 4, bp + (size_t)c * st);
        }
        c += 6; d += 14;
        if (d >= DTOT) { d -= DTOT; c += 1; }
    }
}

// Convert raw fp32 gather buffer -> fp16 A, half2-packed stores.
// 128 rows x 42 slots (41 pairs + 1 single) = 5376 work items.
__device__ __forceinline__ void convert_raw(char* smem, int tid) {
    const float* raw = (const float*)(smem + OFF_RAW);
    char* ah = smem + OFF_A;
    #pragma unroll 3
    for (int s = tid; s < 128 * 42; s += NTHR) {
        int c = s / 42;
        int j = s - c * 42;
        if (j < 41) {
            float v0 = raw[c * DTOT + 2 * j];
            float v1 = raw[c * DTOT + 2 * j + 1];
            *(__half2*)(ah + c * 208 + 4 * j) = __floats2half2_rn(v0, v1);
        } else {
            *(__half*)(ah + c * 208 + 164) = __float2half(raw[c * DTOT + 82]);
        }
    }
}

// ---------------------------------------------------------------------------
// Prologue: W (256x83 fp32) -> g_B hi/lo fp16, row stride STRD, pads zeroed.
__global__ void prep_B_kernel(const float* __restrict__ Wg) {
    int idx = blockIdx.x * 256 + threadIdx.x;
    if (idx >= NOUT * STRD) return;
    int row = idx / STRD;
    int col = idx - row * STRD;
    float v = (col < DTOT) ? Wg[row * DTOT + col] : 0.f;
    __half hi = __float2half(v);
    __half lo = __float2half(v - __half2float(hi));
    g_B[0][idx] = hi;
    g_B[1][idx] = lo;
}

// ---------------------------------------------------------------------------
__global__ void __launch_bounds__(NTHR, 1)
mlfs_kernel(const float* __restrict__ points,
            const float* __restrict__ feat0,
            const float* __restrict__ feat1,
            const float* __restrict__ feat2,
            const float* __restrict__ biasg,
            float* __restrict__ out) {
    extern __shared__ char smem[];
    const uint32_t smem_base = smem_u32(smem);
    const int tid = threadIdx.x;
    const int wid = tid >> 5;
    const int lane = tid & 31;
    const int r = blockIdx.x;

    // ---- setup: B resident copy (async), bias, A-pad zero ----
    {
        const char* src = (const char*)g_B;
        uint32_t dst = smem_base + OFF_BH;
        const int n16 = (2 * NOUT * STRD * 2) / 16;   // 6656
        #pragma unroll 2
        for (int i = tid; i < n16; i += NTHR)
            cp16(dst + i * 16, src + (size_t)i * 16);
    }
    if (tid < 64)
        ((float4*)(smem + OFF_BIAS))[tid] = ((const float4*)biasg)[tid];

    // zero A pad bytes 160..207 of every row (cols 80..103; convert rewrites
    // 160..165 each point): 128 rows, tid<128
    if (tid < 128) {
        float4 z = make_float4(0.f, 0.f, 0.f, 0.f);
        char* base = smem + OFF_A + tid * 208 + 160;
        ((float4*)base)[0] = z; ((float4*)base)[1] = z; ((float4*)base)[2] = z;
    }

    // taps for first point, then issue its gather
    if (tid < DTOT)
        compute_taps(smem, tid, r, points, feat0, feat1, feat2);
    __syncthreads();
    issue_gather(smem, smem_base + OFF_RAW, tid);
    asm volatile("cp.async.commit_group;" ::: "memory");

    // ---- persistent loop ----
    const int wm = wid >> 2;            // 0..3 (M, 32-row tiles)
    const int wn = wid & 3;             // 0..3 (N, 32-col tiles within half)
    const uint32_t lrow = lane & 15;
    const uint32_t kof2 = ((lane >> 4) << 3) * 2;
    const float* bs = (const float*)(smem + OFF_BIAS);

    for (int p = r; p < NPTS_TOTAL; p += NSM) {
        const int pn = p + NSM;
        const bool hasnext = (pn < NPTS_TOTAL);

        asm volatile("cp.async.wait_group 0;" ::: "memory");
        __syncthreads();                 // raw ready; MMA of p-1 done with A

        convert_raw(smem, tid);          // raw -> fp16 A  (raw now free)
        if (tid < DTOT && hasnext)
            compute_taps(smem, tid, pn, points, feat0, feat1, feat2);
        __syncthreads();                 // A ready; taps ready; raw free

        if (hasnext) {
            issue_gather(smem, smem_base + OFF_RAW, tid);   // fire and forget
            asm volatile("cp.async.commit_group;" ::: "memory");
        }

        // ---- two-product MMA; ks-outer, A hoisted across both halves ----
        float acc[2][2][4][4];           // [hh][mt][nt][q] = 64 regs
        #pragma unroll
        for (int hh = 0; hh < 2; ++hh)
            #pragma unroll
            for (int mt = 0; mt < 2; ++mt)
                #pragma unroll
                for (int nt = 0; nt < 4; ++nt)
                    #pragma unroll
                    for (int q = 0; q < 4; ++q) acc[hh][mt][nt][q] = 0.f;

        const uint32_t aAddr0 = smem_base + OFF_A
                              + (wm * 32 + lrow) * 208 + kof2;
        const uint32_t bAddr0 = smem_base + OFF_BH
                              + (wn * 32 + lrow) * 208 + kof2;
        #pragma unroll
        for (int ks = 0; ks < 6; ++ks) {
            uint32_t a[2][4];
            ldsm4(a[0], aAddr0 + ks * 32);
            ldsm4(a[1], aAddr0 + 16 * 208 + ks * 32);
            #pragma unroll
            for (int hh = 0; hh < 2; ++hh) {
                const uint32_t bA = bAddr0 + hh * 128 * 208 + ks * 32;
                uint32_t bh[4][2], bl[4][2], t[4];
                #pragma unroll
                for (int np = 0; np < 2; ++np) {
                    ldsm4(t, bA + np * 16 * 208);
                    bh[2 * np + 0][0] = t[0]; bh[2 * np + 1][0] = t[1];
                    bh[2 * np + 0][1] = t[2]; bh[2 * np + 1][1] = t[3];
                    ldsm4(t, bA + (OFF_BL - OFF_BH) + np * 16 * 208);
                    bl[2 * np + 0][0] = t[0]; bl[2 * np + 1][0] = t[1];
                    bl[2 * np + 0][1] = t[2]; bl[2 * np + 1][1] = t[3];
                }
                #pragma unroll
                for (int mt = 0; mt < 2; ++mt)
                    #pragma unroll
                    for (int nt = 0; nt < 4; ++nt) {
                        hmma(acc[hh][mt][nt], a[mt], bh[nt]);
                        hmma(acc[hh][mt][nt], a[mt], bl[nt]);
                    }
            }
        }

        // ---- epilogue (bias + streaming stores), both halves ----
        float* outp = out + (size_t)p * (CCH * NOUT);
        const int r0 = wm * 32 + (lane >> 2);
        const int c0l = wn * 32 + 2 * (lane & 3);
        #pragma unroll
        for (int hh = 0; hh < 2; ++hh) {
            const int c0 = hh * 128 + c0l;
            float2 bv[4];
            #pragma unroll
            for (int nt = 0; nt < 4; ++nt)
                bv[nt] = *(const float2*)(bs + c0 + nt * 8);
            #pragma unroll
            for (int mt = 0; mt < 2; ++mt) {
                const int row = r0 + mt * 16;
                #pragma unroll
                for (int nt = 0; nt < 4; ++nt) {
                    const int col = c0 + nt * 8;
                    stcs2(outp + (size_t)row * NOUT + col,
                          acc[hh][mt][nt][0] + bv[nt].x,
                          acc[hh][mt][nt][1] + bv[nt].y);
                    stcs2(outp + (size_t)(row + 8) * NOUT + col,
                          acc[hh][mt][nt][2] + bv[nt].x,
                          acc[hh][mt][nt][3] + bv[nt].y);
                }
            }
        }
    }
}

// ---------------------------------------------------------------------------
extern "C" void kernel_launch(void* const* d_in, const int* in_sizes, int n_in,
                              void* d_out, int out_size) {
    const float* points = (const float*)d_in[0];
    const float* feat0  = (const float*)d_in[1];
    const float* feat1  = (const float*)d_in[2];
    const float* feat2  = (const float*)d_in[3];
    const float* Wg     = (const float*)d_in[4];
    const float* biasg  = (const float*)d_in[5];
    float* out = (float*)d_out;

    prep_B_kernel<<<(NOUT * STRD + 255) / 256, 256>>>(Wg);

    cudaFuncSetAttribute(mlfs_kernel,
                         cudaFuncAttributeMaxDynamicSharedMemorySize, SMEM_TOTAL);
    mlfs_kernel<<<NSM, NTHR, SMEM_TOTAL>>>(points, feat0, feat1, feat2,
                                           biasg, out);
}

// round 14
// speedup vs baseline: 1.5095x; 1.5095x over previous
#include <cuda_runtime.h>
#include <cuda_fp16.h>
#include <cstdint>

// ---------------------------------------------------------------------------
// MultiLevelFeatureSampler on GB300 (sm_103a via base-target sm_103 SASS)
//
// Per point: D[128x256] = P[128x83] @ W^T (+ bias); P = gather of 83 taps.
// Two-product fp16 scheme: A -> fp16, B -> fp16 split (bh, bl);
// D = ah*bh + ah*bl  (rel_err ~2e-4, measured).
//
// R14: EXACT R11 MMA structure (proven optimal for this reg budget; R12/R13
// restructurings both regressed).  Non-MMA L1 cuts only:
//  - fused 16B tap entries (ptr+stride via one LDS.128 per gather copy)
//  - half2-packed convert (one 4B STS per 2 taps)
// Persistent CTAs (grid=148, 512 thr); gather of p+1 = fire-and-forget
// cp.async into raw fp32 smem during MMA of p; resident B; st.global.cs.
// ---------------------------------------------------------------------------

#define NSM   148
#define NPTS_TOTAL 2048
#define CCH   128
#define DTOT  83
#define GTOT  (CCH * DTOT)     // 10624 gather elements per point
#define STRD  104              // row stride in fp16 (208 B, ldmatrix conflict-free)
#define NOUT  256
#define NTHR  512

#define H0 93
#define W0 305
#define H1 47
#define W1 153
#define H2 24
#define W2 77

// ---- smem layout (bytes) ----
#define OFF_TAPP    0                              // 83 * 16B {ptr, stride, pad}
#define OFF_BIAS    1408                           // 256 * 4B -> ends 2432
#define OFF_A       2560                           // 128 x 208B = 26624 (fp16)
#define OFF_RAW     (OFF_A + CCH * STRD * 2)       // 29184, 10624 fp32 = 42496
#define OFF_BH      (OFF_RAW + GTOT * 4)           // 71680 (256 x 208B fp16)
#define OFF_BL      (OFF_BH + NOUT * STRD * 2)     // 124928
#define SMEM_TOTAL  (OFF_BL + NOUT * STRD * 2)     // 178176 (~174 KB)

// W split-fp16 scratch, [0]=hi, [1]=lo, row-major 256 x STRD (pads zeroed)
__device__ __align__(16) __half g_B[2][NOUT * STRD];

// ---------------------------------------------------------------------------
__device__ __forceinline__ uint32_t smem_u32(const void* p) {
    uint32_t a;
    asm("{ .reg .u64 t; cvta.to.shared.u64 t, %1; cvt.u32.u64 %0, t; }"
        : "=r"(a) : "l"(p));
    return a;
}

__device__ __forceinline__ void cp16(uint32_t dst, const void* src) {
    asm volatile("cp.async.cg.shared.global [%0], [%1], 16;"
                 :: "r"(dst), "l"(src) : "memory");
}

__device__ __forceinline__ void cp4(uint32_t dst, const void* src) {
    asm volatile("cp.async.ca.shared.global [%0], [%1], 4;"
                 :: "r"(dst), "l"(src) : "memory");
}

__device__ __forceinline__ void ldsm4(uint32_t* r, uint32_t addr) {
    asm volatile("ldmatrix.sync.aligned.m8n8.x4.shared.b16 {%0,%1,%2,%3}, [%4];"
                 : "=r"(r[0]), "=r"(r[1]), "=r"(r[2]), "=r"(r[3]) : "r"(addr));
}

__device__ __forceinline__ void hmma(float* c, const uint32_t* a, const uint32_t* b) {
    asm volatile(
        "mma.sync.aligned.m16n8k16.row.col.f32.f16.f16.f32 "
        "{%0,%1,%2,%3}, {%4,%5,%6,%7}, {%8,%9}, {%0,%1,%2,%3};"
        : "+f"(c[0]), "+f"(c[1]), "+f"(c[2]), "+f"(c[3])
        : "r"(a[0]), "r"(a[1]), "r"(a[2]), "r"(a[3]), "r"(b[0]), "r"(b[1]));
}

__device__ __forceinline__ void stcs2(float* p, float x, float y) {
    asm volatile("st.global.cs.v2.f32 [%0], {%1, %2};"
                 :: "l"(p), "f"(x), "f"(y) : "memory");
}

// Per-tap gather metadata for point pn (called with d < 83).
// Entry: 16B = { const float* ptr (8B), int stride (4B), pad (4B) }.
__device__ __forceinline__ void compute_taps(char* smem, int d, int pn,
                                             const float* __restrict__ points,
                                             const float* __restrict__ feat0,
                                             const float* __restrict__ feat1,
                                             const float* __restrict__ feat2) {
    const float* f; int H, Wd, ks, dd;
    if (d < 49)      { f = feat0; H = H0; Wd = W0; ks = 7; dd = d; }
    else if (d < 74) { f = feat1; H = H1; Wd = W1; ks = 5; dd = d - 49; }
    else             { f = feat2; H = H2; Wd = W2; ks = 3; dd = d - 74; }
    int half = ks >> 1;
    int jj = dd / ks - half;
    int kk = dd % ks - half;
    int bi = pn >> 9;
    float px = points[pn * 2 + 0];
    float py = points[pn * 2 + 1];
    float x = fminf(fmaxf(px * (float)(Wd - 1), 0.f), (float)(Wd - 1));
    float y = fminf(fmaxf(py * (float)(H  - 1), 0.f), (float)(H  - 1));
    int ox = (int)floorf(fminf(fmaxf(x + (float)kk, 0.f), (float)(Wd - 1)));
    int oy = (int)floorf(fminf(fmaxf(y + (float)jj, 0.f), (float)(H  - 1)));
    char* ent = smem + OFF_TAPP + d * 16;
    *(const float**)(ent) = f + (size_t)bi * CCH * H * Wd + (oy * Wd + ox);
    *(int*)(ent + 8) = H * Wd;
}

// Issue all gather cp.asyncs for one point into the raw buffer (no waiting).
// 512 threads: e = tid + 512*i;  512 = 6*83 + 14.  One LDS.128 per copy.
__device__ __forceinline__ void issue_gather(char* smem, uint32_t raw, int tid) {
    int c = tid / DTOT;
    int d = tid - c * DTOT;
    #pragma unroll 7
    for (int i = 0; i < 21; ++i) {
        int e = tid + NTHR * i;
        if (e < GTOT) {
            uint4 te = *(const uint4*)(smem + OFF_TAPP + d * 16);
            const float* bp;
            asm("mov.b64 %0, {%1, %2};" : "=l"(bp) : "r"(te.x), "r"(te.y));
            int st = (int)te.z;
            cp4(raw + e * 4, bp + (size_t)c * st);
        }
        c += 6; d += 14;
        if (d >= DTOT) { d -= DTOT; c += 1; }
    }
}

// Convert raw fp32 gather buffer -> fp16 A, half2-packed stores.
// 128 rows x 42 slots (41 pairs + 1 single) = 5376 work items.
__device__ __forceinline__ void convert_raw(char* smem, int tid) {
    const float* raw = (const float*)(smem + OFF_RAW);
    char* ah = smem + OFF_A;
    #pragma unroll 3
    for (int s = tid; s < 128 * 42; s += NTHR) {
        int c = s / 42;
        int j = s - c * 42;
        if (j < 41) {
            float v0 = raw[c * DTOT + 2 * j];
            float v1 = raw[c * DTOT + 2 * j + 1];
            *(__half2*)(ah + c * 208 + 4 * j) = __floats2half2_rn(v0, v1);
        } else {
            *(__half*)(ah + c * 208 + 164) = __float2half(raw[c * DTOT + 82]);
        }
    }
}

// ---------------------------------------------------------------------------
// Prologue: W (256x83 fp32) -> g_B hi/lo fp16, row stride STRD, pads zeroed.
__global__ void prep_B_kernel(const float* __restrict__ Wg) {
    int idx = blockIdx.x * 256 + threadIdx.x;
    if (idx >= NOUT * STRD) return;
    int row = idx / STRD;
    int col = idx - row * STRD;
    float v = (col < DTOT) ? Wg[row * DTOT + col] : 0.f;
    __half hi = __float2half(v);
    __half lo = __float2half(v - __half2float(hi));
    g_B[0][idx] = hi;
    g_B[1][idx] = lo;
}

// ---------------------------------------------------------------------------
__global__ void __launch_bounds__(NTHR, 1)
mlfs_kernel(const float* __restrict__ points,
            const float* __restrict__ feat0,
            const float* __restrict__ feat1,
            const float* __restrict__ feat2,
            const float* __restrict__ biasg,
            float* __restrict__ out) {
    extern __shared__ char smem[];
    const uint32_t smem_base = smem_u32(smem);
    const int tid = threadIdx.x;
    const int wid = tid >> 5;
    const int lane = tid & 31;
    const int r = blockIdx.x;

    // ---- setup: B resident copy (async), bias, A-pad zero ----
    {
        const char* src = (const char*)g_B;
        uint32_t dst = smem_base + OFF_BH;
        const int n16 = (2 * NOUT * STRD * 2) / 16;   // 6656
        #pragma unroll 2
        for (int i = tid; i < n16; i += NTHR)
            cp16(dst + i * 16, src + (size_t)i * 16);
    }
    if (tid < 64)
        ((float4*)(smem + OFF_BIAS))[tid] = ((const float4*)biasg)[tid];

    // zero A pad bytes 160..207 of every row (cols 80..103; convert rewrites
    // 160..165 each point): 128 rows, tid<128
    if (tid < 128) {
        float4 z = make_float4(0.f, 0.f, 0.f, 0.f);
        char* base = smem + OFF_A + tid * 208 + 160;
        ((float4*)base)[0] = z; ((float4*)base)[1] = z; ((float4*)base)[2] = z;
    }

    // taps for first point, then issue its gather
    if (tid < DTOT)
        compute_taps(smem, tid, r, points, feat0, feat1, feat2);
    __syncthreads();
    issue_gather(smem, smem_base + OFF_RAW, tid);
    asm volatile("cp.async.commit_group;" ::: "memory");

    // ---- persistent loop ----
    const int wm = wid >> 2;            // 0..3 (M, 32-row tiles)
    const int wn = wid & 3;             // 0..3 (N, 32-col tiles within half)
    const uint32_t lrow = lane & 15;
    const uint32_t kof2 = ((lane >> 4) << 3) * 2;
    const float* bs = (const float*)(smem + OFF_BIAS);

    for (int p = r; p < NPTS_TOTAL; p += NSM) {
        const int pn = p + NSM;
        const bool hasnext = (pn < NPTS_TOTAL);

        asm volatile("cp.async.wait_group 0;" ::: "memory");
        __syncthreads();                 // raw ready; MMA of p-1 done with A

        convert_raw(smem, tid);          // raw -> fp16 A  (raw now free)
        if (tid < DTOT && hasnext)
            compute_taps(smem, tid, pn, points, feat0, feat1, feat2);
        __syncthreads();                 // A ready; taps ready; raw free

        if (hasnext) {
            issue_gather(smem, smem_base + OFF_RAW, tid);   // fire and forget
            asm volatile("cp.async.commit_group;" ::: "memory");
        }

        // ---- two-product MMA + epilogue (EXACT R11 structure) ----
        float* outp = out + (size_t)p * (CCH * NOUT);
        #pragma unroll
        for (int hh = 0; hh < 2; ++hh) {
            float acc[2][4][4];
            #pragma unroll
            for (int mt = 0; mt < 2; ++mt)
                #pragma unroll
                for (int nt = 0; nt < 4; ++nt)
                    #pragma unroll
                    for (int q = 0; q < 4; ++q) acc[mt][nt][q] = 0.f;

            const uint32_t aAddr0 = smem_base + OFF_A
                                  + (wm * 32 + lrow) * 208 + kof2;
            const uint32_t bAddrH = smem_base + OFF_BH
                                  + (hh * 128 + wn * 32 + lrow) * 208 + kof2;
            #pragma unroll
            for (int ks = 0; ks < 6; ++ks) {
                uint32_t a[2][4], bh[4][2], bl[4][2], t[4];
                #pragma unroll
                for (int mt = 0; mt < 2; ++mt)
                    ldsm4(a[mt], aAddr0 + mt * 16 * 208 + ks * 32);
                #pragma unroll
                for (int np = 0; np < 2; ++np) {
                    ldsm4(t, bAddrH + np * 16 * 208 + ks * 32);
                    bh[2 * np + 0][0] = t[0]; bh[2 * np + 1][0] = t[1];
                    bh[2 * np + 0][1] = t[2]; bh[2 * np + 1][1] = t[3];
                    ldsm4(t, bAddrH + (OFF_BL - OFF_BH) + np * 16 * 208 + ks * 32);
                    bl[2 * np + 0][0] = t[0]; bl[2 * np + 1][0] = t[1];
                    bl[2 * np + 0][1] = t[2]; bl[2 * np + 1][1] = t[3];
                }
                #pragma unroll
                for (int mt = 0; mt < 2; ++mt)
                    #pragma unroll
                    for (int nt = 0; nt < 4; ++nt) {
                        hmma(acc[mt][nt], a[mt], bh[nt]);
                        hmma(acc[mt][nt], a[mt], bl[nt]);
                    }
            }

            // epilogue for this 128-col half (streaming stores)
            const int r0 = wm * 32 + (lane >> 2);
            const int c0 = wn * 32 + 2 * (lane & 3);
            float2 bv[4];
            #pragma unroll
            for (int nt = 0; nt < 4; ++nt)
                bv[nt] = *(const float2*)(bs + hh * 128 + c0 + nt * 8);
            float* oph = outp + hh * 128;
            #pragma unroll
            for (int mt = 0; mt < 2; ++mt) {
                const int row = r0 + mt * 16;
                #pragma unroll
                for (int nt = 0; nt < 4; ++nt) {
                    const int col = c0 + nt * 8;
                    stcs2(oph + (size_t)row * NOUT + col,
                          acc[mt][nt][0] + bv[nt].x, acc[mt][nt][1] + bv[nt].y);
                    stcs2(oph + (size_t)(row + 8) * NOUT + col,
                          acc[mt][nt][2] + bv[nt].x, acc[mt][nt][3] + bv[nt].y);
                }
            }
        }
    }
}

// ---------------------------------------------------------------------------
extern "C" void kernel_launch(void* const* d_in, const int* in_sizes, int n_in,
                              void* d_out, int out_size) {
    const float* points = (const float*)d_in[0];
    const float* feat0  = (const float*)d_in[1];
    const float* feat1  = (const float*)d_in[2];
    const float* feat2  = (const float*)d_in[3];
    const float* Wg     = (const float*)d_in[4];
    const float* biasg  = (const float*)d_in[5];
    float* out = (float*)d_out;

    prep_B_kernel<<<(NOUT * STRD + 255) / 256, 256>>>(Wg);

    cudaFuncSetAttribute(mlfs_kernel,
                         cudaFuncAttributeMaxDynamicSharedMemorySize, SMEM_TOTAL);
    mlfs_kernel<<<NSM, NTHR, SMEM_TOTAL>>>(points, feat0, feat1, feat2,
                                           biasg, out);
}